// round 15
// baseline (speedup 1.0000x reference)
#include <cuda_runtime.h>
#include <cuda_fp16.h>

#define BATCH    128
#define NPTS     16384
#define GL       48
#define GW       20
#define GH       18
#define SLAB     (GL * GW * GH)        // 17280 source voxels
#define HALF_L   2.4f
#define HALF_W   1.0f

// padded pair table: x in [0,48], y in [0,20], z in [0,17]
#define PYD      (GW + 1)              // 21
#define XSTRIDE  (PYD * GH)            // 378
#define PSLAB    ((GL + 1) * XSTRIDE)  // 18522 half2 entries

#define THREADS    1024
#define GRID_CTAS  296                 // 148 SMs * 2 CTAs, one exact wave
#define SMEM_BYTES (PSLAB * 4)         // 74088 B

#define XLIM 47.99999f
#define YLIM 19.99999f
#define ZLIM 17.99999f

// cross-CTA reduction state (zero-init in module image; reset by last CTA)
__device__ float        g_acc   = 0.0f;
__device__ unsigned int g_count = 0u;

__global__ __launch_bounds__(THREADS, 2)
void pose_loss_kernel(const float* __restrict__ voxels,
                      const float* __restrict__ pts,
                      const float* __restrict__ hgt,
                      float* __restrict__ out)
{
    extern __shared__ __half2 svox[];  // svox[(x*21+y)*18+z] = (v[z], v[z+1 or z if z==17])
    __shared__ float warp_red[THREADS / 32];

    const int g   = blockIdx.x;
    const int tid = threadIdx.x;

    // ---- balanced split: batches 0..39 -> 3 CTAs, 40..127 -> 2 CTAs ----
    int batch, rank, nch;
    if (g < 120) { batch = g / 3;             rank = g % 3;         nch = 3; }
    else         { batch = 40 + (g - 120) / 2; rank = (g - 120) % 2; nch = 2; }
    const int pstart = (rank * NPTS / nch) & ~3;
    const int pend   = (rank == nch - 1) ? NPTS : (((rank + 1) * NPTS / nch) & ~3);

    const float* __restrict__ vsrc = voxels + (size_t)batch * SLAB;

    // ---- stage z-pair slab into padded layout (coalesced float4 reads) ----
    {
        const float4* __restrict__ vsrc4 = (const float4*)vsrc;
        for (int i = tid; i < SLAB / 4; i += THREADS) {
            const int i4 = i * 4;
            const int xs  = i4 / (GW * GH);          // 360 elems per x-slice
            const int rem = i4 - xs * (GW * GH);
            const int dst = xs * XSTRIDE + rem;      // float4 never crosses x (360%4==0)

            const float4 a = vsrc4[i];
            int nidx = i4 + 4; if (nidx >= SLAB) nidx = SLAB - 1;
            const float nxt = vsrc[nidx];
            const int mz = (i4 + 1) % GH;            // z(i4)==17 <=> mz==0, etc.
            const float n0 = (mz == 0)  ? a.x : a.y;
            const float n1 = (mz == 17) ? a.y : a.z;
            const float n2 = (mz == 16) ? a.z : a.w;
            const float n3 = (mz == 15) ? a.w : nxt;
            svox[dst + 0] = __floats2half2_rn(a.x, n0);
            svox[dst + 1] = __floats2half2_rn(a.y, n1);
            svox[dst + 2] = __floats2half2_rn(a.z, n2);
            svox[dst + 3] = __floats2half2_rn(a.w, n3);
        }
    }

    // ---- y-pad (row y=20 := y=19) straight from GLOBAL: no smem dependency ----
    for (int i = tid; i < GL * GH; i += THREADS) {
        const int xs = i / GH, z = i - xs * GH;
        const float cur = vsrc[(xs * GW + (GW - 1)) * GH + z];
        const float nx  = (z < GH - 1) ? vsrc[(xs * GW + (GW - 1)) * GH + z + 1] : cur;
        svox[xs * XSTRIDE + GW * GH + z] = __floats2half2_rn(cur, nx);
    }

    // ---- x-pad (slice x=48 := x=47, incl. y=20 row) from GLOBAL ----
    for (int j = tid; j < XSTRIDE; j += THREADS) {
        const int y = j / GH, z = j - y * GH;
        const int ys = (y < GW) ? y : (GW - 1);
        const float cur = vsrc[((GL - 1) * GW + ys) * GH + z];
        const float nx  = (z < GH - 1) ? vsrc[((GL - 1) * GW + ys) * GH + z + 1] : cur;
        svox[GL * XSTRIDE + j] = __floats2half2_rn(cur, nx);
    }
    __syncthreads();   // single barrier: all fill loops are independent

    float acc = 0.0f;
    const size_t bbase = (size_t)batch * NPTS;

    for (int p = pstart + tid * 4; p < pend; p += THREADS * 4) {
        const size_t gp = bbase + p;
        const float4* __restrict__ pf = (const float4*)(pts + gp * 3);
        const float4 a = pf[0], b = pf[1], c = pf[2];
        const float4 h = *(const float4*)(hgt + gp);

        const float PX[4]  = { a.x, a.w, b.z, c.y };
        const float PY4[4] = { a.y, b.x, b.w, c.z };
        const float PZ[4]  = { a.z, b.y, c.x, c.w };
        const float HH[4]  = { h.x, h.y, h.z, h.w };

        #pragma unroll
        for (int k = 0; k < 4; ++k) {
            // folded: (p + off)*10, clamped in float — padded table keeps
            // indices valid and reproduces ref's clamp semantics
            const float xc = fminf(fmaxf(fmaf(PX[k], 10.0f, 24.0f), 0.0f), XLIM);
            const float yc = fminf(fmaxf(fmaf(PY4[k], 10.0f, 10.0f), 0.0f), YLIM);
            const float zc = fminf(fmaxf(fmaf(HH[k], 5.0f, PZ[k] * 10.0f), 0.0f), ZLIM);

            const float xmf = floorf(xc);
            const float ymf = floorf(yc);
            const float zmf = floorf(zc);

            const float tx = xc - xmf;
            const float ty = yc - ymf;
            const float tz = zc - zmf;
            const float sx = 1.0f - tx;
            const float sy = 1.0f - ty;
            const float sz = 1.0f - tz;

            const int ix = (int)xmf;
            const int iy = (int)ymf;
            const int iz = (int)zmf;

            const int c00 = (ix * PYD + iy) * GH + iz;
            const __half2 h00 = svox[c00];
            const __half2 h01 = svox[c00 + GH];
            const __half2 h10 = svox[c00 + XSTRIDE];
            const __half2 h11 = svox[c00 + XSTRIDE + GH];

            const __half2 w00 = __float2half2_rn(sx * sy);
            const __half2 w01 = __float2half2_rn(sx * ty);
            const __half2 w10 = __float2half2_rn(tx * sy);
            const __half2 w11 = __float2half2_rn(tx * ty);

            __half2 acc2 = __hmul2(h00, w00);
            acc2 = __hfma2(h01, w01, acc2);
            acc2 = __hfma2(h10, w10, acc2);
            acc2 = __hfma2(h11, w11, acc2);

            const float2 fa = __half22float2(acc2);
            const float sdf = fmaf(fa.y, tz, fa.x * sz);

            const float ax = fabsf(sdf);
            acc += (ax < 1.0f) ? (0.5f * sdf * sdf) : (ax - 0.5f);
        }
    }

    // ---- block reduction ----
    #pragma unroll
    for (int off = 16; off > 0; off >>= 1)
        acc += __shfl_xor_sync(0xFFFFFFFFu, acc, off);

    const int lane = tid & 31;
    const int wid  = tid >> 5;
    if (lane == 0) warp_red[wid] = acc;
    __syncthreads();

    if (wid == 0) {
        float s = (lane < THREADS / 32) ? warp_red[lane] : 0.0f;
        #pragma unroll
        for (int off = 16; off > 0; off >>= 1)
            s += __shfl_xor_sync(0xFFFFFFFFu, s, off);

        // ---- cross-CTA reduction: last CTA writes out and resets state ----
        if (lane == 0) {
            atomicAdd(&g_acc, s);
            __threadfence();
            const unsigned int n = atomicAdd(&g_count, 1u);
            if (n == GRID_CTAS - 1) {
                const float total = *((volatile float*)&g_acc);
                out[0] = total * (1.0f / ((float)BATCH * (float)NPTS));
                g_acc   = 0.0f;      // restore invariant for next graph replay
                g_count = 0u;
                __threadfence();
            }
        }
    }
}

extern "C" void kernel_launch(void* const* d_in, const int* in_sizes, int n_in,
                              void* d_out, int out_size)
{
    const float* voxels = (const float*)d_in[0];
    const float* pts    = (const float*)d_in[1];
    const float* hgt    = (const float*)d_in[2];
    float* out          = (float*)d_out;

    static int configured = 0;
    if (!configured) {
        cudaFuncSetAttribute(pose_loss_kernel,
                             cudaFuncAttributeMaxDynamicSharedMemorySize,
                             SMEM_BYTES);
        configured = 1;
    }

    pose_loss_kernel<<<GRID_CTAS, THREADS, SMEM_BYTES>>>(voxels, pts, hgt, out);
}

// round 17
// speedup vs baseline: 1.0497x; 1.0497x over previous
#include <cuda_runtime.h>
#include <cuda_fp16.h>

#define BATCH    128
#define NPTS     16384
#define GL       48
#define GW       20
#define GH       18
#define SLAB     (GL * GW * GH)        // 17280 source voxels
#define HALF_L   2.4f
#define HALF_W   1.0f

// padded pair table: x in [0,48], y in [0,20], z in [0,17]
#define PYD      (GW + 1)              // 21
#define XSTRIDE  (PYD * GH)            // 378
#define PSLAB    ((GL + 1) * XSTRIDE)  // 18522 half2 entries

#define THREADS    1024
#define GRID_CTAS  296                 // 148 SMs * 2 CTAs, one exact wave
#define SMEM_BYTES (PSLAB * 4)         // 74088 B

#define XLIM 47.99999f
#define YLIM 19.99999f
#define ZLIM 17.99999f

__global__ __launch_bounds__(THREADS, 2)
void pose_loss_kernel(const float* __restrict__ voxels,
                      const float* __restrict__ pts,
                      const float* __restrict__ hgt,
                      float* __restrict__ out)
{
    extern __shared__ __half2 svox[];  // svox[(x*21+y)*18+z] = (v[z], v[z+1 or z if z==17])
    __shared__ float warp_red[THREADS / 32];

    const int g   = blockIdx.x;
    const int tid = threadIdx.x;

    // ---- balanced split: batches 0..39 -> 3 CTAs, 40..127 -> 2 CTAs ----
    int batch, rank, nch;
    if (g < 120) { batch = g / 3;             rank = g % 3;         nch = 3; }
    else         { batch = 40 + (g - 120) / 2; rank = (g - 120) % 2; nch = 2; }
    const int pstart = (rank * NPTS / nch) & ~3;
    const int pend   = (rank == nch - 1) ? NPTS : (((rank + 1) * NPTS / nch) & ~3);

    const float* __restrict__ vsrc = voxels + (size_t)batch * SLAB;

    // ---- stage z-pair slab into padded layout (coalesced float4 reads) ----
    {
        const float4* __restrict__ vsrc4 = (const float4*)vsrc;
        for (int i = tid; i < SLAB / 4; i += THREADS) {
            const int i4 = i * 4;
            const int xs  = i4 / (GW * GH);          // 360 elems per x-slice
            const int rem = i4 - xs * (GW * GH);
            const int dst = xs * XSTRIDE + rem;      // float4 never crosses x (360%4==0)

            const float4 a = vsrc4[i];
            int nidx = i4 + 4; if (nidx >= SLAB) nidx = SLAB - 1;
            const float nxt = vsrc[nidx];
            const int mz = (i4 + 1) % GH;            // z(i4)==17 <=> mz==0, etc.
            const float n0 = (mz == 0)  ? a.x : a.y;
            const float n1 = (mz == 17) ? a.y : a.z;
            const float n2 = (mz == 16) ? a.z : a.w;
            const float n3 = (mz == 15) ? a.w : nxt;
            svox[dst + 0] = __floats2half2_rn(a.x, n0);
            svox[dst + 1] = __floats2half2_rn(a.y, n1);
            svox[dst + 2] = __floats2half2_rn(a.z, n2);
            svox[dst + 3] = __floats2half2_rn(a.w, n3);
        }
    }
    __syncthreads();

    // ---- pads: BOTH read only stage-written smem -> single barrier after ----
    // y-pad: row y=20 := row y=19 for x in [0,48)
    for (int i = tid; i < GL * GH; i += THREADS) {
        const int xs = i / GH, z = i - xs * GH;
        svox[xs * XSTRIDE + GW * GH + z] = svox[xs * XSTRIDE + (GW - 1) * GH + z];
    }
    // x-pad: slice x=48 := slice x=47; its y=20 row sourced from y=19 (same value)
    for (int j = tid; j < XSTRIDE; j += THREADS) {
        const int y = j / GH, z = j - y * GH;
        const int ys = (y < GW) ? y : (GW - 1);
        svox[GL * XSTRIDE + j] = svox[(GL - 1) * XSTRIDE + ys * GH + z];
    }
    __syncthreads();

    float acc0 = 0.0f, acc1 = 0.0f;
    const size_t bbase = (size_t)batch * NPTS;

    for (int p = pstart + tid * 4; p < pend; p += THREADS * 4) {
        const size_t gp = bbase + p;
        const float4* __restrict__ pf = (const float4*)(pts + gp * 3);
        const float4 a = pf[0], b = pf[1], c = pf[2];
        const float4 h = *(const float4*)(hgt + gp);

        const float PX[4]  = { a.x, a.w, b.z, c.y };
        const float PY4[4] = { a.y, b.x, b.w, c.z };
        const float PZ[4]  = { a.z, b.y, c.x, c.w };
        const float HH[4]  = { h.x, h.y, h.z, h.w };

        #pragma unroll
        for (int k = 0; k < 4; ++k) {
            // folded: (p + off)*10, clamped in float — padded table keeps
            // indices valid and reproduces ref's clamp semantics
            const float xc = fminf(fmaxf(fmaf(PX[k], 10.0f, 24.0f), 0.0f), XLIM);
            const float yc = fminf(fmaxf(fmaf(PY4[k], 10.0f, 10.0f), 0.0f), YLIM);
            const float zc = fminf(fmaxf(fmaf(HH[k], 5.0f, PZ[k] * 10.0f), 0.0f), ZLIM);

            const float xmf = floorf(xc);
            const float ymf = floorf(yc);
            const float zmf = floorf(zc);

            const float tx = xc - xmf;
            const float ty = yc - ymf;
            const float tz = zc - zmf;
            const float sx = 1.0f - tx;
            const float sy = 1.0f - ty;
            const float sz = 1.0f - tz;

            const int ix = (int)xmf;
            const int iy = (int)ymf;
            const int iz = (int)zmf;

            const int c00 = (ix * PYD + iy) * GH + iz;
            const __half2 h00 = svox[c00];
            const __half2 h01 = svox[c00 + GH];
            const __half2 h10 = svox[c00 + XSTRIDE];
            const __half2 h11 = svox[c00 + XSTRIDE + GH];

            const __half2 w00 = __float2half2_rn(sx * sy);
            const __half2 w01 = __float2half2_rn(sx * ty);
            const __half2 w10 = __float2half2_rn(tx * sy);
            const __half2 w11 = __float2half2_rn(tx * ty);

            // two parallel chains, one merge: depth 3 instead of 4
            const __half2 e0 = __hfma2(h01, w01, __hmul2(h00, w00));
            const __half2 e1 = __hfma2(h11, w11, __hmul2(h10, w10));
            const __half2 acc2 = __hadd2(e0, e1);

            const float2 fa = __half22float2(acc2);
            const float sdf = fmaf(fa.y, tz, fa.x * sz);

            const float ax = fabsf(sdf);
            const float hub = (ax < 1.0f) ? (0.5f * sdf * sdf) : (ax - 0.5f);
            if (k & 1) acc1 += hub; else acc0 += hub;
        }
    }

    float acc = acc0 + acc1;

    // ---- block reduction ----
    #pragma unroll
    for (int off = 16; off > 0; off >>= 1)
        acc += __shfl_xor_sync(0xFFFFFFFFu, acc, off);

    const int lane = tid & 31;
    const int wid  = tid >> 5;
    if (lane == 0) warp_red[wid] = acc;
    __syncthreads();

    if (wid == 0) {
        float s = (lane < THREADS / 32) ? warp_red[lane] : 0.0f;
        #pragma unroll
        for (int off = 16; off > 0; off >>= 1)
            s += __shfl_xor_sync(0xFFFFFFFFu, s, off);
        if (lane == 0)
            atomicAdd(out, s * (1.0f / ((float)BATCH * (float)NPTS)));
    }
}

extern "C" void kernel_launch(void* const* d_in, const int* in_sizes, int n_in,
                              void* d_out, int out_size)
{
    const float* voxels = (const float*)d_in[0];
    const float* pts    = (const float*)d_in[1];
    const float* hgt    = (const float*)d_in[2];
    float* out          = (float*)d_out;

    static int configured = 0;
    if (!configured) {
        cudaFuncSetAttribute(pose_loss_kernel,
                             cudaFuncAttributeMaxDynamicSharedMemorySize,
                             SMEM_BYTES);
        configured = 1;
    }

    cudaMemsetAsync(out, 0, sizeof(float));

    pose_loss_kernel<<<GRID_CTAS, THREADS, SMEM_BYTES>>>(voxels, pts, hgt, out);
}